// round 1
// baseline (speedup 1.0000x reference)
#include <cuda_runtime.h>
#include <cuda_bf16.h>
#include <math.h>

#define MAXN 100000
#define IN_DIM 512

// ---------------- scratch (no allocation allowed -> __device__ globals) ------
__device__ float g_bufA[MAXN * 64];
__device__ float g_bufB[MAXN * 64];
__device__ int   g_rp[MAXN + 1];
__device__ float g_stats[128];   // [0..63] sum, [64..127] sumsq

// ---------------- f32x2 packed FMA (Blackwell FFMA2) -------------------------
__device__ __forceinline__ float2 ffma2(float2 a, float2 b, float2 c) {
    unsigned long long ua = *reinterpret_cast<unsigned long long*>(&a);
    unsigned long long ub = *reinterpret_cast<unsigned long long*>(&b);
    unsigned long long uc = *reinterpret_cast<unsigned long long*>(&c);
    unsigned long long ud;
    asm("fma.rn.f32x2 %0, %1, %2, %3;" : "=l"(ud) : "l"(ua), "l"(ub), "l"(uc));
    return *reinterpret_cast<float2*>(&ud);
}

// ---------------- row_ptr from sorted edge_row (lower_bound) -----------------
__global__ void build_rowptr(const int* __restrict__ erow, int E, int n,
                             int* __restrict__ rp) {
    int i = blockIdx.x * blockDim.x + threadIdx.x;
    if (i > n) return;
    int lo = 0, hi = E;
    while (lo < hi) {
        int mid = (lo + hi) >> 1;
        if (erow[mid] < i) lo = mid + 1; else hi = mid;
    }
    rp[i] = lo;
}

// ---------------- GEMM1: [M,512] x [512,64] -> [M,64], fp32 via FFMA2 --------
__global__ void __launch_bounds__(256) gemm1_kernel(
    const float* __restrict__ A, const float* __restrict__ B,
    float* __restrict__ C, int M) {
    const int K = 512, NN = 64, BK = 16, BM = 128;
    __shared__ float As[BK][BM + 4];   // transposed: [k][m]
    __shared__ float Bs[BK][NN];

    int tid = threadIdx.x;
    int tr = tid >> 3;                 // 0..31 (4 rows each)
    int tc = tid & 7;                  // 0..7  (8 cols each)
    int rowBase = blockIdx.x * BM;

    float2 acc[4][4];
#pragma unroll
    for (int i = 0; i < 4; ++i)
#pragma unroll
        for (int j = 0; j < 4; ++j) acc[i][j] = make_float2(0.f, 0.f);

    int la_row = tid >> 2;             // 0..63 (loads 2 rows: +0, +64)
    int la_k   = (tid & 3) * 4;
    int lb_k   = tid >> 4;             // 0..15
    int lb_c   = (tid & 15) * 4;

    for (int kt = 0; kt < K; kt += BK) {
#pragma unroll
        for (int rr = 0; rr < 2; ++rr) {
            int r = la_row + rr * 64;
            int grow = rowBase + r;
            float4 v = make_float4(0.f, 0.f, 0.f, 0.f);
            if (grow < M)
                v = *(const float4*)(A + (size_t)grow * K + kt + la_k);
            As[la_k + 0][r] = v.x;
            As[la_k + 1][r] = v.y;
            As[la_k + 2][r] = v.z;
            As[la_k + 3][r] = v.w;
        }
        float4 bv = *(const float4*)(B + (size_t)(kt + lb_k) * NN + lb_c);
        *(float4*)&Bs[lb_k][lb_c] = bv;
        __syncthreads();

#pragma unroll
        for (int k = 0; k < BK; ++k) {
            float4 a4 = *(const float4*)&As[k][tr * 4];
            float2 b2[4];
            *(float4*)&b2[0] = *(const float4*)&Bs[k][tc * 8];
            *(float4*)&b2[2] = *(const float4*)&Bs[k][tc * 8 + 4];
            float av[4] = {a4.x, a4.y, a4.z, a4.w};
#pragma unroll
            for (int i = 0; i < 4; ++i) {
                float2 ad = make_float2(av[i], av[i]);
#pragma unroll
                for (int j = 0; j < 4; ++j) acc[i][j] = ffma2(ad, b2[j], acc[i][j]);
            }
        }
        __syncthreads();
    }

#pragma unroll
    for (int i = 0; i < 4; ++i) {
        int grow = rowBase + tr * 4 + i;
        if (grow < M) {
            float* cp = C + (size_t)grow * 64 + tc * 8;
            *(float4*)cp       = *(float4*)&acc[i][0];
            *(float4*)(cp + 4) = *(float4*)&acc[i][2];
        }
    }
}

// ---------------- SpMM: out[i] = sum_e val[e]*sup[col[e]] (CSR, warp/node) ---
template <int D>
__global__ void spmm_kernel(const float* __restrict__ sup,
                            const int* __restrict__ ecol,
                            const float* __restrict__ ev,
                            const int* __restrict__ rp,
                            float* __restrict__ out, int n) {
    int gw = (blockIdx.x * blockDim.x + threadIdx.x) >> 5;
    int lane = threadIdx.x & 31;

    if (D == 16) {
        // two nodes per warp (half-warp each) to avoid wasted gather bandwidth
        int node = gw * 2 + (lane >> 4);
        int sl = lane & 15;
        if (node >= n) return;
        int s = rp[node], e = rp[node + 1];
        float acc = 0.f;
        int j = s;
        for (; j + 4 <= e; j += 4) {
            int c0 = ecol[j], c1 = ecol[j + 1], c2 = ecol[j + 2], c3 = ecol[j + 3];
            float v0 = ev[j], v1 = ev[j + 1], v2 = ev[j + 2], v3 = ev[j + 3];
            acc = fmaf(v0, sup[(size_t)c0 * 16 + sl], acc);
            acc = fmaf(v1, sup[(size_t)c1 * 16 + sl], acc);
            acc = fmaf(v2, sup[(size_t)c2 * 16 + sl], acc);
            acc = fmaf(v3, sup[(size_t)c3 * 16 + sl], acc);
        }
        for (; j < e; ++j)
            acc = fmaf(ev[j], sup[(size_t)ecol[j] * 16 + sl], acc);
        out[(size_t)node * 16 + sl] = acc;
        return;
    }

    if (gw >= n) return;
    int s = rp[gw], e = rp[gw + 1];
    float acc0 = 0.f, acc1 = 0.f;
    int j = s;
    for (; j + 4 <= e; j += 4) {
        int c0 = ecol[j], c1 = ecol[j + 1], c2 = ecol[j + 2], c3 = ecol[j + 3];
        float v0 = ev[j], v1 = ev[j + 1], v2 = ev[j + 2], v3 = ev[j + 3];
        const float* r0 = sup + (size_t)c0 * D;
        const float* r1 = sup + (size_t)c1 * D;
        const float* r2 = sup + (size_t)c2 * D;
        const float* r3 = sup + (size_t)c3 * D;
        acc0 = fmaf(v0, r0[lane], acc0);
        acc0 = fmaf(v1, r1[lane], acc0);
        acc0 = fmaf(v2, r2[lane], acc0);
        acc0 = fmaf(v3, r3[lane], acc0);
        if (D > 32) {
            if (lane + 32 < D) {
                acc1 = fmaf(v0, r0[lane + 32], acc1);
                acc1 = fmaf(v1, r1[lane + 32], acc1);
                acc1 = fmaf(v2, r2[lane + 32], acc1);
                acc1 = fmaf(v3, r3[lane + 32], acc1);
            }
        }
    }
    for (; j < e; ++j) {
        int c = ecol[j]; float v = ev[j];
        const float* r = sup + (size_t)c * D;
        acc0 = fmaf(v, r[lane], acc0);
        if (D > 32 && lane + 32 < D) acc1 = fmaf(v, r[lane + 32], acc1);
    }
    if (lane < D) out[(size_t)gw * D + lane] = acc0;
    if (D > 32 && lane + 32 < D) out[(size_t)gw * D + lane + 32] = acc1;
}

// ---------------- column stats: sum & sumsq per channel ----------------------
__global__ void zero_stats() {
    if (threadIdx.x < 128) g_stats[threadIdx.x] = 0.f;
}

template <int D>
__global__ void col_stats(const float* __restrict__ h, int n) {
    __shared__ float ss[256], sq[256];
    const int REPS = 256 / D;
    int tid = threadIdx.x;
    int ch = tid % D;
    int rep = tid / D;
    int chunk = (n + gridDim.x - 1) / gridDim.x;
    int r0 = blockIdx.x * chunk;
    int r1 = min(n, r0 + chunk);
    float s = 0.f, q = 0.f;
    for (int r = r0 + rep; r < r1; r += REPS) {
        float v = h[(size_t)r * D + ch];
        s += v;
        q = fmaf(v, v, q);
    }
    ss[tid] = s; sq[tid] = q;
    __syncthreads();
    if (tid < D) {
        float S = 0.f, Q = 0.f;
#pragma unroll
        for (int i = 0; i < REPS; ++i) { S += ss[tid + i * D]; Q += sq[tid + i * D]; }
        atomicAdd(&g_stats[ch], S);
        atomicAdd(&g_stats[64 + ch], Q);
    }
}

// ---------------- BN (training-mode batch stats) + ELU, in-place -------------
template <int D>
__global__ void bn_elu(float* __restrict__ h,
                       const float* __restrict__ gamma,
                       const float* __restrict__ beta, int n) {
    int i = blockIdx.x * blockDim.x + threadIdx.x;
    if (i >= n * D) return;
    int ch = i % D;
    float invn = 1.0f / (float)n;
    float mean = g_stats[ch] * invn;
    float var  = g_stats[64 + ch] * invn - mean * mean;
    float inv  = rsqrtf(var + 1e-5f);
    float y = (h[i] - mean) * inv * gamma[ch] + beta[ch];
    h[i] = y > 0.f ? y : expm1f(y);
}

// ---------------- small GEMM: [n,IN] x [IN,OUT] -> [n,OUT], warp per node ----
template <int IN, int OUT>
__global__ void gemm_small(const float* __restrict__ h,
                           const float* __restrict__ W,
                           float* __restrict__ out, int n) {
    __shared__ float Ws[IN * OUT + 64];   // padded: lanes >= OUT read junk, discarded
    for (int i = threadIdx.x; i < IN * OUT + 64; i += blockDim.x)
        Ws[i] = (i < IN * OUT) ? W[i] : 0.f;
    __syncthreads();
    int gw = (blockIdx.x * blockDim.x + threadIdx.x) >> 5;
    int lane = threadIdx.x & 31;
    if (gw >= n) return;
    const float* hr = h + (size_t)gw * IN;
    float acc0 = 0.f, acc1 = 0.f;
#pragma unroll
    for (int k = 0; k < IN; k += 4) {
        float4 h4 = *(const float4*)(hr + k);
        acc0 = fmaf(h4.x, Ws[(k + 0) * OUT + lane], acc0);
        acc0 = fmaf(h4.y, Ws[(k + 1) * OUT + lane], acc0);
        acc0 = fmaf(h4.z, Ws[(k + 2) * OUT + lane], acc0);
        acc0 = fmaf(h4.w, Ws[(k + 3) * OUT + lane], acc0);
        if (OUT > 32) {
            acc1 = fmaf(h4.x, Ws[(k + 0) * OUT + lane + 32], acc1);
            acc1 = fmaf(h4.y, Ws[(k + 1) * OUT + lane + 32], acc1);
            acc1 = fmaf(h4.z, Ws[(k + 2) * OUT + lane + 32], acc1);
            acc1 = fmaf(h4.w, Ws[(k + 3) * OUT + lane + 32], acc1);
        }
    }
    if (lane < OUT) out[(size_t)gw * OUT + lane] = acc0;
    if (OUT > 32 && lane + 32 < OUT) out[(size_t)gw * OUT + lane + 32] = acc1;
}

// ---------------- log_softmax over 40 classes, warp per node -----------------
__global__ void logsoftmax40(const float* __restrict__ h, float* __restrict__ out, int n) {
    int gw = (blockIdx.x * blockDim.x + threadIdx.x) >> 5;
    int lane = threadIdx.x & 31;
    if (gw >= n) return;
    const float* r = h + (size_t)gw * 40;
    float a0 = r[lane];
    float a1 = (lane < 8) ? r[32 + lane] : __int_as_float(0xff800000);
    float m = fmaxf(a0, a1);
#pragma unroll
    for (int o = 16; o; o >>= 1) m = fmaxf(m, __shfl_xor_sync(0xffffffffu, m, o));
    float e0 = expf(a0 - m);
    float e1 = (lane < 8) ? expf(a1 - m) : 0.f;
    float s = e0 + e1;
#pragma unroll
    for (int o = 16; o; o >>= 1) s += __shfl_xor_sync(0xffffffffu, s, o);
    float lse = logf(s) + m;
    out[(size_t)gw * 40 + lane] = a0 - lse;
    if (lane < 8) out[(size_t)gw * 40 + 32 + lane] = a1 - lse;
}

// ---------------- launch ------------------------------------------------------
static inline int dg(long long t, int b) { return (int)((t + b - 1) / b); }

extern "C" void kernel_launch(void* const* d_in, const int* in_sizes, int n_in,
                              void* d_out, int out_size) {
    const float* x    = (const float*)d_in[0];
    const int*   erow = (const int*)d_in[1];
    const int*   ecol = (const int*)d_in[2];
    const float* ev   = (const float*)d_in[3];
    const float* W1   = (const float*)d_in[4];
    const float* W2   = (const float*)d_in[5];
    const float* W3   = (const float*)d_in[6];
    const float* W4   = (const float*)d_in[7];
    const float* g1   = (const float*)d_in[8];
    const float* b1   = (const float*)d_in[9];
    const float* g2   = (const float*)d_in[10];
    const float* b2   = (const float*)d_in[11];
    const float* g3   = (const float*)d_in[12];
    const float* b3   = (const float*)d_in[13];

    int n = in_sizes[0] / IN_DIM;
    int E = in_sizes[1];
    float* out = (float*)d_out;

    float* hA; float* hB; int* rp;
    cudaGetSymbolAddress((void**)&hA, g_bufA);
    cudaGetSymbolAddress((void**)&hB, g_bufB);
    cudaGetSymbolAddress((void**)&rp, g_rp);

    const int TB = 256;
    const int STATS_BLOCKS = 512;

    // CSR row pointers (edge_row is sorted)
    build_rowptr<<<dg(n + 1, TB), TB>>>(erow, E, n, rp);

    // ---- layer 1: x @ W1 -> spmm -> bn+elu ----
    gemm1_kernel<<<dg(n, 128), 256>>>(x, W1, hA, n);
    spmm_kernel<64><<<dg((long long)n * 32, TB), TB>>>(hA, ecol, ev, rp, hB, n);
    zero_stats<<<1, 128>>>();
    col_stats<64><<<STATS_BLOCKS, 256>>>(hB, n);
    bn_elu<64><<<dg((long long)n * 64, TB), TB>>>(hB, g1, b1, n);

    // ---- layer 2: 64 -> 32 ----
    gemm_small<64, 32><<<dg((long long)n * 32, TB), TB>>>(hB, W2, hA, n);
    spmm_kernel<32><<<dg((long long)n * 32, TB), TB>>>(hA, ecol, ev, rp, hB, n);
    zero_stats<<<1, 128>>>();
    col_stats<32><<<STATS_BLOCKS, 256>>>(hB, n);
    bn_elu<32><<<dg((long long)n * 32, TB), TB>>>(hB, g2, b2, n);

    // ---- layer 3: 32 -> 16 ----
    gemm_small<32, 16><<<dg((long long)n * 32, TB), TB>>>(hB, W3, hA, n);
    spmm_kernel<16><<<dg((long long)((n + 1) / 2) * 32, TB), TB>>>(hA, ecol, ev, rp, hB, n);
    zero_stats<<<1, 128>>>();
    col_stats<16><<<STATS_BLOCKS, 256>>>(hB, n);
    bn_elu<16><<<dg((long long)n * 16, TB), TB>>>(hB, g3, b3, n);

    // ---- layer 4: 16 -> 40, spmm, log_softmax ----
    gemm_small<16, 40><<<dg((long long)n * 32, TB), TB>>>(hB, W4, hA, n);
    spmm_kernel<40><<<dg((long long)n * 32, TB), TB>>>(hA, ecol, ev, rp, hB, n);
    logsoftmax40<<<dg((long long)n * 32, TB), TB>>>(hB, out, n);
}